// round 1
// baseline (speedup 1.0000x reference)
#include <cuda_runtime.h>
#include <cuda_bf16.h>
#include <cstdint>
#include <cstdio>

// Problem constants
#define BB 2
#define SS 2048
#define DM 2048
#define NH 32
#define NKV 8
#define HD 64

// Scratch (allocation-free rule: __device__ globals)
__device__ float g_q[(size_t)BB * SS * NH * HD];    // [B,S,H,64]  = [4096, 2048]
__device__ float g_k[(size_t)BB * SS * NKV * HD];   // [B,S,KV,64] = [4096, 512]
__device__ float g_v[(size_t)BB * SS * NKV * HD];
__device__ float g_att[(size_t)BB * SS * NH * HD];  // attention output, [4096, 2048]

// ---------------------------------------------------------------------------
// SGEMM: C[M,N] = A[M,K] @ B[K,N], row-major, all dims multiples of tile.
// 128x128 block tile, BK=8, 256 threads, 8x8 register tile per thread.
// ---------------------------------------------------------------------------
__global__ __launch_bounds__(256) void sgemm_kernel(
    const float* __restrict__ A, const float* __restrict__ B,
    float* __restrict__ C, int M, int N, int K)
{
    __shared__ float As[8][128];
    __shared__ float Bs[8][128];

    const int tid = threadIdx.x;
    const int bm = blockIdx.y * 128;
    const int bn = blockIdx.x * 128;

    const int a_row = tid >> 1;          // 0..127
    const int a_col = (tid & 1) * 4;     // 0 or 4
    const int b_row = tid >> 5;          // 0..7
    const int b_col = (tid & 31) * 4;    // 0..124

    const int ty = tid >> 4;             // 0..15
    const int tx = tid & 15;             // 0..15

    float acc[8][8];
#pragma unroll
    for (int i = 0; i < 8; i++)
#pragma unroll
        for (int j = 0; j < 8; j++) acc[i][j] = 0.f;

    const float* Aptr = A + (size_t)(bm + a_row) * K + a_col;
    const float* Bptr = B + (size_t)b_row * N + bn + b_col;

    for (int k0 = 0; k0 < K; k0 += 8) {
        float4 av = *(const float4*)(Aptr + k0);
        As[a_col + 0][a_row] = av.x;
        As[a_col + 1][a_row] = av.y;
        As[a_col + 2][a_row] = av.z;
        As[a_col + 3][a_row] = av.w;
        *(float4*)&Bs[b_row][b_col] = *(const float4*)(Bptr + (size_t)k0 * N);
        __syncthreads();

#pragma unroll
        for (int k = 0; k < 8; k++) {
            float ar[8], br[8];
            *(float4*)&ar[0] = *(const float4*)&As[k][ty * 4];
            *(float4*)&ar[4] = *(const float4*)&As[k][64 + ty * 4];
            *(float4*)&br[0] = *(const float4*)&Bs[k][tx * 4];
            *(float4*)&br[4] = *(const float4*)&Bs[k][64 + tx * 4];
#pragma unroll
            for (int i = 0; i < 8; i++)
#pragma unroll
                for (int j = 0; j < 8; j++)
                    acc[i][j] = fmaf(ar[i], br[j], acc[i][j]);
        }
        __syncthreads();
    }

#pragma unroll
    for (int i = 0; i < 8; i++) {
        const int r = bm + ((i < 4) ? (ty * 4 + i) : (64 + ty * 4 + i - 4));
        float4 c0 = make_float4(acc[i][0], acc[i][1], acc[i][2], acc[i][3]);
        float4 c1 = make_float4(acc[i][4], acc[i][5], acc[i][6], acc[i][7]);
        *(float4*)&C[(size_t)r * N + bn + tx * 4] = c0;
        *(float4*)&C[(size_t)r * N + bn + 64 + tx * 4] = c1;
    }
}

// ---------------------------------------------------------------------------
// RoPE in-place on [B, S, heads, 64] tensor. One thread per (b,s,h,pair).
// shift = log2(32*heads) so s = (i >> shift) & (S-1)
// ---------------------------------------------------------------------------
__global__ void rope_kernel(float* __restrict__ t,
                            const float* __restrict__ cs,
                            const float* __restrict__ sn,
                            int shift, int total)
{
    int i = blockIdx.x * 256 + threadIdx.x;
    if (i >= total) return;
    int p = i & 31;
    int s = (i >> shift) & (SS - 1);
    float2 v = *(float2*)(t + (size_t)i * 2);
    float c = cs[s * 32 + p];
    float si = sn[s * 32 + p];
    float2 o;
    o.x = v.x * c - v.y * si;
    o.y = v.x * si + v.y * c;
    *(float2*)(t + (size_t)i * 2) = o;
}

// ---------------------------------------------------------------------------
// Flash attention (causal, GQA). Block = (q-tile of 64 rows, head h, batch b).
// 256 threads: thread = (row = tid>>2, quad = tid&3).
// Q row kept in registers; K/V tiles in smem (pad 68 for conflict-free
// quad-strided float4 access); P exchanged via shfl within quads.
// ---------------------------------------------------------------------------
__global__ __launch_bounds__(256) void attn_kernel(
    const float* __restrict__ Q, const float* __restrict__ Kg,
    const float* __restrict__ Vg, float* __restrict__ O)
{
    __shared__ float Ks[64][68];
    __shared__ float Vs[64][68];

    const int m0 = blockIdx.x * 64;
    const int h = blockIdx.y;
    const int b = blockIdx.z;
    const int kvh = h >> 2;  // GQA: 4 q-heads per kv-head
    const int tid = threadIdx.x;
    const int row = tid >> 2;
    const int quad = tid & 3;
    const int lane = tid & 31;
    const int lbase = lane & 28;

    // Q row -> registers
    float qreg[64];
    {
        const float* qp = Q + ((size_t)(b * SS + m0 + row)) * (NH * HD) + h * HD;
#pragma unroll
        for (int t = 0; t < 16; t++) {
            float4 v = *(const float4*)(qp + t * 4);
            qreg[t * 4 + 0] = v.x;
            qreg[t * 4 + 1] = v.y;
            qreg[t * 4 + 2] = v.z;
            qreg[t * 4 + 3] = v.w;
        }
    }

    float acc[16];
#pragma unroll
    for (int i = 0; i < 16; i++) acc[i] = 0.f;
    float mrow = -1e30f, lrow = 0.f;
    const int qpos = m0 + row;

    const size_t kvbase = (size_t)b * SS * (NKV * HD) + kvh * HD;

    for (int n0 = 0; n0 <= m0; n0 += 64) {
        __syncthreads();  // previous iteration done with Ks/Vs
        {
            const float* kp = Kg + kvbase + (size_t)(n0 + row) * (NKV * HD) + quad * 16;
            const float* vp = Vg + kvbase + (size_t)(n0 + row) * (NKV * HD) + quad * 16;
#pragma unroll
            for (int t = 0; t < 4; t++) {
                *(float4*)&Ks[row][quad * 16 + t * 4] = *(const float4*)(kp + t * 4);
                *(float4*)&Vs[row][quad * 16 + t * 4] = *(const float4*)(vp + t * 4);
            }
        }
        __syncthreads();

        // scores: this thread owns j = jj*4 + quad (interleaved for bank spread)
        float s[16];
#pragma unroll
        for (int jj = 0; jj < 16; jj++) {
            const int j = jj * 4 + quad;
            float sum = 0.f;
#pragma unroll
            for (int t = 0; t < 16; t++) {
                float4 k4 = *(const float4*)&Ks[j][t * 4];
                sum = fmaf(qreg[t * 4 + 0], k4.x, sum);
                sum = fmaf(qreg[t * 4 + 1], k4.y, sum);
                sum = fmaf(qreg[t * 4 + 2], k4.z, sum);
                sum = fmaf(qreg[t * 4 + 3], k4.w, sum);
            }
            s[jj] = (n0 + j <= qpos) ? sum * 0.125f : -1e30f;
        }

        // online softmax (row shared by 4 threads of a quad)
        float tmax = s[0];
#pragma unroll
        for (int jj = 1; jj < 16; jj++) tmax = fmaxf(tmax, s[jj]);
        tmax = fmaxf(tmax, __shfl_xor_sync(0xffffffffu, tmax, 1));
        tmax = fmaxf(tmax, __shfl_xor_sync(0xffffffffu, tmax, 2));
        const float mnew = fmaxf(mrow, tmax);
        const float corr = __expf(mrow - mnew);
        mrow = mnew;
        float tsum = 0.f;
#pragma unroll
        for (int jj = 0; jj < 16; jj++) {
            s[jj] = __expf(s[jj] - mnew);
            tsum += s[jj];
        }
        tsum += __shfl_xor_sync(0xffffffffu, tsum, 1);
        tsum += __shfl_xor_sync(0xffffffffu, tsum, 2);
        lrow = lrow * corr + tsum;
#pragma unroll
        for (int i = 0; i < 16; i++) acc[i] *= corr;

        // PV: need p for all 64 j; pull from quad peers via shfl
#pragma unroll
        for (int jj = 0; jj < 16; jj++) {
#pragma unroll
            for (int q2 = 0; q2 < 4; q2++) {
                const float pj = __shfl_sync(0xffffffffu, s[jj], lbase | q2, 32);
                const int j = jj * 4 + q2;
#pragma unroll
                for (int t = 0; t < 4; t++) {
                    const int ch = t * 4 + quad;  // this thread's d-chunks
                    float4 v4 = *(const float4*)&Vs[j][ch * 4];
                    acc[t * 4 + 0] = fmaf(pj, v4.x, acc[t * 4 + 0]);
                    acc[t * 4 + 1] = fmaf(pj, v4.y, acc[t * 4 + 1]);
                    acc[t * 4 + 2] = fmaf(pj, v4.z, acc[t * 4 + 2]);
                    acc[t * 4 + 3] = fmaf(pj, v4.w, acc[t * 4 + 3]);
                }
            }
        }
    }

    const float inv = 1.f / lrow;
    float* op = O + ((size_t)(b * SS + qpos)) * (NH * HD) + h * HD;
#pragma unroll
    for (int t = 0; t < 4; t++) {
        const int ch = t * 4 + quad;
        float4 o4 = make_float4(acc[t * 4 + 0] * inv, acc[t * 4 + 1] * inv,
                                acc[t * 4 + 2] * inv, acc[t * 4 + 3] * inv);
        *(float4*)(op + ch * 4) = o4;
    }
}

// ---------------------------------------------------------------------------
// Launch
// inputs: 0=x, 1=freqs_cos, 2=freqs_sin, 3=mask(unused), 4=wq, 5=wk, 6=wv, 7=wo
// ---------------------------------------------------------------------------
extern "C" void kernel_launch(void* const* d_in, const int* in_sizes, int n_in,
                              void* d_out, int out_size)
{
    const float* x = (const float*)d_in[0];
    const float* fcos = (const float*)d_in[1];
    const float* fsin = (const float*)d_in[2];
    const float* wq = (const float*)d_in[4];
    const float* wk = (const float*)d_in[5];
    const float* wv = (const float*)d_in[6];
    const float* wo = (const float*)d_in[7];
    float* out = (float*)d_out;

    float *q, *k, *v, *att;
    cudaGetSymbolAddress((void**)&q, g_q);
    cudaGetSymbolAddress((void**)&k, g_k);
    cudaGetSymbolAddress((void**)&v, g_v);
    cudaGetSymbolAddress((void**)&att, g_att);

    const int M = BB * SS;  // 4096

    // QKV projections
    sgemm_kernel<<<dim3((NH * HD) / 128, M / 128), 256>>>(x, wq, q, M, NH * HD, DM);
    sgemm_kernel<<<dim3((NKV * HD) / 128, M / 128), 256>>>(x, wk, k, M, NKV * HD, DM);
    sgemm_kernel<<<dim3((NKV * HD) / 128, M / 128), 256>>>(x, wv, v, M, NKV * HD, DM);

    // RoPE (in place). pairs per tensor:
    {
        int totq = BB * SS * NH * 32;   // 4194304, shift = log2(32*32)=10
        int totk = BB * SS * NKV * 32;  // 1048576, shift = log2(32*8)=8
        rope_kernel<<<(totq + 255) / 256, 256>>>(q, fcos, fsin, 10, totq);
        rope_kernel<<<(totk + 255) / 256, 256>>>(k, fcos, fsin, 8, totk);
    }

    // Attention
    attn_kernel<<<dim3(SS / 64, NH, BB), 256>>>(q, k, v, att);

    // Output projection
    sgemm_kernel<<<dim3(DM / 128, M / 128), 256>>>(att, wo, out, M, DM, DM);
}

// round 3
// speedup vs baseline: 2.9802x; 2.9802x over previous
#include <cuda_runtime.h>
#include <cstdint>

// Problem constants
#define BB 2
#define SS 2048
#define DM 2048
#define NH 32
#define NKV 8
#define HD 64

// ---------------------------------------------------------------------------
// Scratch (allocation-free rule: __device__ globals)
// ---------------------------------------------------------------------------
__device__ __align__(1024) float g_q[(size_t)BB * SS * NH * HD];
__device__ __align__(1024) float g_k[(size_t)BB * SS * NKV * HD];
__device__ __align__(1024) float g_v[(size_t)BB * SS * NKV * HD];
__device__ __align__(1024) float g_att[(size_t)BB * SS * NH * HD];
__device__ __align__(1024) float g_xr[(size_t)BB * SS * DM];
__device__ __align__(1024) float g_wqT[(size_t)(NH * HD) * DM];
__device__ __align__(1024) float g_wkT[(size_t)(NKV * HD) * DM];
__device__ __align__(1024) float g_wvT[(size_t)(NKV * HD) * DM];
__device__ __align__(1024) float g_woT[(size_t)DM * DM];

// ---------------------------------------------------------------------------
// Helpers
// ---------------------------------------------------------------------------
__device__ __forceinline__ uint32_t smem_u32(const void* p) {
    uint32_t a;
    asm("{ .reg .u64 t; cvta.to.shared.u64 t, %1; cvt.u32.u64 %0, t; }" : "=r"(a) : "l"(p));
    return a;
}
__device__ __forceinline__ float rna_tf32(float v) {
    uint32_t r;
    asm("cvt.rna.tf32.f32 %0, %1;" : "=r"(r) : "f"(v));
    return __uint_as_float(r);
}
__device__ __forceinline__ void cp_async16(uint32_t smem, const void* gmem) {
    asm volatile("cp.async.cg.shared.global [%0], [%1], 16;" :: "r"(smem), "l"(gmem));
}
#define CP_COMMIT() asm volatile("cp.async.commit_group;" ::: "memory")
#define CP_WAIT(n)  asm volatile("cp.async.wait_group %0;" :: "n"(n) : "memory")

// m16n8k8 tf32 MMA (sm_80+ baseline feature; runs on Blackwell legacy HMMA pipe)
__device__ __forceinline__ void mma16n8k8(float* d, const uint32_t* a, const uint32_t* b) {
    asm volatile(
        "mma.sync.aligned.m16n8k8.row.col.f32.tf32.tf32.f32 "
        "{%0,%1,%2,%3}, {%4,%5,%6,%7}, {%8,%9}, {%0,%1,%2,%3};"
        : "+f"(d[0]), "+f"(d[1]), "+f"(d[2]), "+f"(d[3])
        : "r"(a[0]), "r"(a[1]), "r"(a[2]), "r"(a[3]), "r"(b[0]), "r"(b[1]));
}

// ---------------------------------------------------------------------------
// tf32 mma.sync GEMM: C[M,N] = A[M,K] @ Bt[N,K]^T  (both K-major, tf32-rounded)
// BM=BN=128, BK=32, 256 threads / 8 warps (warp tile 32x64), 3-stage cp.async.
// smem rows padded to 36 floats -> all fragment LDS conflict-free.
// ---------------------------------------------------------------------------
#define GSTAGE 9216  // floats per stage (A 128*36 + B 128*36)
#define GEMM_SMEM (3 * GSTAGE * 4)

__global__ __launch_bounds__(256) void gemm_tf32_kernel(
    const float* __restrict__ A, const float* __restrict__ Bt,
    float* __restrict__ C, int M, int N, int K)
{
    extern __shared__ float sm[];
    const int tid = threadIdx.x;
    const int wid = tid >> 5, lid = tid & 31;
    const int wm = wid & 3, wn = wid >> 2;       // 4x2 warp grid
    const int lr = lid >> 2, lc = lid & 3;
    const int bm = blockIdx.y * 128, bn = blockIdx.x * 128;

    const float* Ag = A + (size_t)bm * K;
    const float* Bg = Bt + (size_t)bn * K;
    const uint32_t sb = smem_u32(sm);

    float acc[2][8][4];
#pragma unroll
    for (int mt = 0; mt < 2; mt++)
#pragma unroll
        for (int nt = 0; nt < 8; nt++)
#pragma unroll
            for (int i = 0; i < 4; i++) acc[mt][nt][i] = 0.f;

    auto load_stage = [&](int s) {
        const int st = s - (s / 3) * 3;
        const float* Ab = Ag + s * 32;
        const float* Bb = Bg + s * 32;
#pragma unroll
        for (int i = 0; i < 4; i++) {
            int c = tid + i * 256;
            int row = c >> 3, cc = (c & 7) * 4;
            cp_async16(sb + (uint32_t)(st * GSTAGE + row * 36 + cc) * 4,
                       Ab + (size_t)row * K + cc);
            cp_async16(sb + (uint32_t)(st * GSTAGE + 4608 + row * 36 + cc) * 4,
                       Bb + (size_t)row * K + cc);
        }
    };

    const int nk = K / 32;
#pragma unroll
    for (int s = 0; s < 3; s++) { if (s < nk) load_stage(s); CP_COMMIT(); }

    for (int s = 0; s < nk; s++) {
        CP_WAIT(2);
        __syncthreads();
        const int st = s - (s / 3) * 3;
        const float* As = sm + st * GSTAGE + (wm * 32 + lr) * 36 + lc;
        const float* Bs = sm + st * GSTAGE + 4608 + (wn * 64 + lr) * 36 + lc;
#pragma unroll
        for (int kk = 0; kk < 4; kk++) {
            uint32_t af[2][4], bf[8][2];
#pragma unroll
            for (int mt = 0; mt < 2; mt++) {
                const float* p = As + mt * 16 * 36 + kk * 8;
                af[mt][0] = __float_as_uint(p[0]);
                af[mt][1] = __float_as_uint(p[8 * 36]);
                af[mt][2] = __float_as_uint(p[4]);
                af[mt][3] = __float_as_uint(p[8 * 36 + 4]);
            }
#pragma unroll
            for (int nt = 0; nt < 8; nt++) {
                const float* p = Bs + nt * 8 * 36 + kk * 8;
                bf[nt][0] = __float_as_uint(p[0]);
                bf[nt][1] = __float_as_uint(p[4]);
            }
#pragma unroll
            for (int mt = 0; mt < 2; mt++)
#pragma unroll
                for (int nt = 0; nt < 8; nt++)
                    mma16n8k8(acc[mt][nt], af[mt], bf[nt]);
        }
        __syncthreads();
        if (s + 3 < nk) load_stage(s + 3);
        CP_COMMIT();
    }

    // epilogue: lane holds rows (lr, lr+8), cols 2*lc, 2*lc+1 per 16x8 tile
#pragma unroll
    for (int mt = 0; mt < 2; mt++) {
        const int r0 = bm + wm * 32 + mt * 16 + lr;
#pragma unroll
        for (int nt = 0; nt < 8; nt++) {
            const int col = bn + wn * 64 + nt * 8 + lc * 2;
            *(float2*)&C[(size_t)r0 * N + col] =
                make_float2(acc[mt][nt][0], acc[mt][nt][1]);
            *(float2*)&C[(size_t)(r0 + 8) * N + col] =
                make_float2(acc[mt][nt][2], acc[mt][nt][3]);
        }
    }
}

// ---------------------------------------------------------------------------
// Elementwise fp32 -> tf32 (RNA)
// ---------------------------------------------------------------------------
__global__ void round_tf32_kernel(const float4* __restrict__ in,
                                  float4* __restrict__ out, int n4)
{
    int i = blockIdx.x * 256 + threadIdx.x;
    if (i >= n4) return;
    float4 v = in[i];
    v.x = rna_tf32(v.x); v.y = rna_tf32(v.y);
    v.z = rna_tf32(v.z); v.w = rna_tf32(v.w);
    out[i] = v;
}

// ---------------------------------------------------------------------------
// Transpose + RNA round: out[C,R] = rna(in[R,C]^T)
// ---------------------------------------------------------------------------
__global__ void transpose_rna_kernel(const float* __restrict__ in,
                                     float* __restrict__ out, int R, int C)
{
    __shared__ float t[32][33];
    const int bx = blockIdx.x * 32;
    const int by = blockIdx.y * 32;
    const int x = bx + threadIdx.x;
#pragma unroll
    for (int i = threadIdx.y; i < 32; i += 8)
        t[i][threadIdx.x] = in[(size_t)(by + i) * C + x];
    __syncthreads();
    const int xo = by + threadIdx.x;
#pragma unroll
    for (int i = threadIdx.y; i < 32; i += 8)
        out[(size_t)(bx + i) * R + xo] = rna_tf32(t[threadIdx.x][i]);
}

// ---------------------------------------------------------------------------
// RoPE in-place + optional scale + tf32 RNA round
// ---------------------------------------------------------------------------
__global__ void rope_kernel(float* __restrict__ t,
                            const float* __restrict__ cs,
                            const float* __restrict__ sn,
                            int shift, int total, float scale)
{
    int i = blockIdx.x * 256 + threadIdx.x;
    if (i >= total) return;
    int p = i & 31;
    int s = (i >> shift) & (SS - 1);
    float2 v = *(float2*)(t + (size_t)i * 2);
    float c = cs[s * 32 + p];
    float si = sn[s * 32 + p];
    float2 o;
    o.x = rna_tf32(scale * (v.x * c - v.y * si));
    o.y = rna_tf32(scale * (v.x * si + v.y * c));
    *(float2*)(t + (size_t)i * 2) = o;
}

// ---------------------------------------------------------------------------
// Flash attention (causal, GQA) via mma.sync tf32.
// Block = 64 q-rows x head x batch. 4 warps, warp owns 16 rows.
// Q frags persistent in regs; K_s(68)/V_s(72) pads -> conflict-free B-frags;
// P frags built from S-accumulator layout via shfl. fp32 online softmax.
// ---------------------------------------------------------------------------
__global__ __launch_bounds__(128) void attn_kernel(
    const float* __restrict__ Q, const float* __restrict__ Kg,
    const float* __restrict__ Vg, float* __restrict__ O)
{
    __shared__ float Ks[64 * 68];
    __shared__ float Vs[64 * 72];

    const int m0 = blockIdx.x * 64;
    const int h = blockIdx.y;
    const int b = blockIdx.z;
    const int kvh = h >> 2;
    const int tid = threadIdx.x;
    const int w = tid >> 5, lid = tid & 31;
    const int lr = lid >> 2, lc = lid & 3;
    const int row0 = m0 + w * 16 + lr;   // second row-half is row0+8

    // Persistent Q fragments (already scaled by 1/8 and tf32-rounded in rope)
    uint32_t qa[8][4];
    {
        const float* q0 = Q + ((size_t)(b * SS + row0) * NH + h) * HD;
        const float* q1 = q0 + (size_t)8 * NH * HD;
#pragma unroll
        for (int kk = 0; kk < 8; kk++) {
            qa[kk][0] = __float_as_uint(q0[kk * 8 + lc]);
            qa[kk][1] = __float_as_uint(q1[kk * 8 + lc]);
            qa[kk][2] = __float_as_uint(q0[kk * 8 + lc + 4]);
            qa[kk][3] = __float_as_uint(q1[kk * 8 + lc + 4]);
        }
    }

    float oacc[8][4];
#pragma unroll
    for (int nt = 0; nt < 8; nt++)
#pragma unroll
        for (int i = 0; i < 4; i++) oacc[nt][i] = 0.f;
    float mst0 = -1e30f, mst1 = -1e30f, lst0 = 0.f, lst1 = 0.f;

    const size_t kvs = NKV * HD;  // 512
    const float* Kbase = Kg + (size_t)b * SS * kvs + kvh * HD;
    const float* Vbase = Vg + (size_t)b * SS * kvs + kvh * HD;

    for (int n0 = 0; n0 <= m0; n0 += 64) {
        __syncthreads();
        for (int i = tid; i < 1024; i += 128) {
            int j = i >> 4, cc = (i & 15) * 4;
            *(float4*)&Ks[j * 68 + cc] = *(const float4*)(Kbase + (size_t)(n0 + j) * kvs + cc);
            *(float4*)&Vs[j * 72 + cc] = *(const float4*)(Vbase + (size_t)(n0 + j) * kvs + cc);
        }
        __syncthreads();

        // S = Q K^T  (per-lane: rows lr/lr+8, cols 2lc,2lc+1 per 8-col n-tile)
        float s[8][4];
#pragma unroll
        for (int nt = 0; nt < 8; nt++)
#pragma unroll
            for (int i = 0; i < 4; i++) s[nt][i] = 0.f;
#pragma unroll
        for (int kk = 0; kk < 8; kk++) {
#pragma unroll
            for (int nt = 0; nt < 8; nt++) {
                uint32_t kb[2];
                const float* p = &Ks[(nt * 8 + lr) * 68 + kk * 8 + lc];
                kb[0] = __float_as_uint(p[0]);
                kb[1] = __float_as_uint(p[4]);
                mma16n8k8(s[nt], qa[kk], kb);
            }
        }

        // causal mask (diagonal tile only)
        if (n0 == m0) {
#pragma unroll
            for (int nt = 0; nt < 8; nt++) {
                const int key = n0 + nt * 8 + lc * 2;
                if (key > row0) s[nt][0] = -1e30f;
                if (key + 1 > row0) s[nt][1] = -1e30f;
                if (key > row0 + 8) s[nt][2] = -1e30f;
                if (key + 1 > row0 + 8) s[nt][3] = -1e30f;
            }
        }

        // online softmax (row shared by a quad: shfl_xor 1,2)
        float mx0 = -1e30f, mx1 = -1e30f;
#pragma unroll
        for (int nt = 0; nt < 8; nt++) {
            mx0 = fmaxf(mx0, fmaxf(s[nt][0], s[nt][1]));
            mx1 = fmaxf(mx1, fmaxf(s[nt][2], s[nt][3]));
        }
        mx0 = fmaxf(mx0, __shfl_xor_sync(0xffffffffu, mx0, 1));
        mx0 = fmaxf(mx0, __shfl_xor_sync(0xffffffffu, mx0, 2));
        mx1 = fmaxf(mx1, __shfl_xor_sync(0xffffffffu, mx1, 1));
        mx1 = fmaxf(mx1, __shfl_xor_sync(0xffffffffu, mx1, 2));
        const float mn0 = fmaxf(mst0, mx0), mn1 = fmaxf(mst1, mx1);
        const float corr0 = __expf(mst0 - mn0), corr1 = __expf(mst1 - mn1);
        mst0 = mn0; mst1 = mn1;
        float sum0 = 0.f, sum1 = 0.f;
#pragma unroll
        for (int nt = 0; nt < 8; nt++) {
            s[nt][0] = __expf(s[nt][0] - mn0); sum0 += s[nt][0];
            s[nt][1] = __expf(s[nt][1] - mn0); sum0 += s[nt][1];
            s[nt][2] = __expf(s[nt][2] - mn1); sum1 += s[nt][2];
            s[nt][3] = __expf(s[nt][3] - mn1); sum1 += s[nt][3];
        }
        sum0 += __shfl_xor_sync(0xffffffffu, sum0, 1);
        sum0 += __shfl_xor_sync(0xffffffffu, sum0, 2);
        sum1 += __shfl_xor_sync(0xffffffffu, sum1, 1);
        sum1 += __shfl_xor_sync(0xffffffffu, sum1, 2);
        lst0 = lst0 * corr0 + sum0;
        lst1 = lst1 * corr1 + sum1;
#pragma unroll
        for (int nt = 0; nt < 8; nt++) {
            oacc[nt][0] *= corr0; oacc[nt][1] *= corr0;
            oacc[nt][2] *= corr1; oacc[nt][3] *= corr1;
        }

        // O += P V : build P A-frags from S layout via shfl
        const int sl = (lid & ~3) | (lc >> 1);
        const int sl2 = sl | 2;
#pragma unroll
        for (int kk = 0; kk < 8; kk++) {
            float v00 = __shfl_sync(0xffffffffu, s[kk][0], sl);
            float v01 = __shfl_sync(0xffffffffu, s[kk][1], sl);
            float v10 = __shfl_sync(0xffffffffu, s[kk][2], sl);
            float v11 = __shfl_sync(0xffffffffu, s[kk][3], sl);
            float w00 = __shfl_sync(0xffffffffu, s[kk][0], sl2);
            float w01 = __shfl_sync(0xffffffffu, s[kk][1], sl2);
            float w10 = __shfl_sync(0xffffffffu, s[kk][2], sl2);
            float w11 = __shfl_sync(0xffffffffu, s[kk][3], sl2);
            uint32_t pa[4];
            pa[0] = __float_as_uint((lc & 1) ? v01 : v00);
            pa[1] = __float_as_uint((lc & 1) ? v11 : v10);
            pa[2] = __float_as_uint((lc & 1) ? w01 : w00);
            pa[3] = __float_as_uint((lc & 1) ? w11 : w10);
#pragma unroll
            for (int nt = 0; nt < 8; nt++) {
                uint32_t vb[2];
                const float* p = &Vs[(kk * 8 + lc) * 72 + nt * 8 + lr];
                vb[0] = __float_as_uint(p[0]);
                vb[1] = __float_as_uint(p[4 * 72]);
                mma16n8k8(oacc[nt], pa, vb);
            }
        }
    }

    const float inv0 = 1.f / lst0, inv1 = 1.f / lst1;
    float* o0 = O + ((size_t)(b * SS + row0) * NH + h) * HD;
    float* o1 = o0 + (size_t)8 * NH * HD;
#pragma unroll
    for (int nt = 0; nt < 8; nt++) {
        const int col = nt * 8 + lc * 2;
        *(float2*)&o0[col] = make_float2(rna_tf32(oacc[nt][0] * inv0),
                                         rna_tf32(oacc[nt][1] * inv0));
        *(float2*)&o1[col] = make_float2(rna_tf32(oacc[nt][2] * inv1),
                                         rna_tf32(oacc[nt][3] * inv1));
    }
}

// ---------------------------------------------------------------------------
// Launch. inputs: 0=x, 1=freqs_cos, 2=freqs_sin, 3=mask(unused),
//                 4=wq, 5=wk, 6=wv, 7=wo
// ---------------------------------------------------------------------------
extern "C" void kernel_launch(void* const* d_in, const int* in_sizes, int n_in,
                              void* d_out, int out_size)
{
    const float* x = (const float*)d_in[0];
    const float* fcos = (const float*)d_in[1];
    const float* fsin = (const float*)d_in[2];
    const float* wq = (const float*)d_in[4];
    const float* wk = (const float*)d_in[5];
    const float* wv = (const float*)d_in[6];
    const float* wo = (const float*)d_in[7];
    float* out = (float*)d_out;

    float *q, *k, *v, *att, *xr, *wqT, *wkT, *wvT, *woT;
    cudaGetSymbolAddress((void**)&q, g_q);
    cudaGetSymbolAddress((void**)&k, g_k);
    cudaGetSymbolAddress((void**)&v, g_v);
    cudaGetSymbolAddress((void**)&att, g_att);
    cudaGetSymbolAddress((void**)&xr, g_xr);
    cudaGetSymbolAddress((void**)&wqT, g_wqT);
    cudaGetSymbolAddress((void**)&wkT, g_wkT);
    cudaGetSymbolAddress((void**)&wvT, g_wvT);
    cudaGetSymbolAddress((void**)&woT, g_woT);

    static bool attr_set = false;
    if (!attr_set) {
        cudaFuncSetAttribute(gemm_tf32_kernel,
                             cudaFuncAttributeMaxDynamicSharedMemorySize, GEMM_SMEM);
        attr_set = true;
    }

    const int M = BB * SS;  // 4096

    // tf32-round activations; transpose+round weights to [N,K]
    {
        int n4 = (BB * SS * DM) / 4;
        round_tf32_kernel<<<(n4 + 255) / 256, 256>>>((const float4*)x, (float4*)xr, n4);
    }
    transpose_rna_kernel<<<dim3((NH * HD) / 32, DM / 32), dim3(32, 8)>>>(wq, wqT, DM, NH * HD);
    transpose_rna_kernel<<<dim3((NKV * HD) / 32, DM / 32), dim3(32, 8)>>>(wk, wkT, DM, NKV * HD);
    transpose_rna_kernel<<<dim3((NKV * HD) / 32, DM / 32), dim3(32, 8)>>>(wv, wvT, DM, NKV * HD);
    transpose_rna_kernel<<<dim3(DM / 32, DM / 32), dim3(32, 8)>>>(wo, woT, DM, DM);

    // QKV projections (mma.sync tf32)
    gemm_tf32_kernel<<<dim3((NH * HD) / 128, M / 128), 256, GEMM_SMEM>>>(xr, wqT, q, M, NH * HD, DM);
    gemm_tf32_kernel<<<dim3((NKV * HD) / 128, M / 128), 256, GEMM_SMEM>>>(xr, wkT, k, M, NKV * HD, DM);
    gemm_tf32_kernel<<<dim3((NKV * HD) / 128, M / 128), 256, GEMM_SMEM>>>(xr, wvT, v, M, NKV * HD, DM);

    // RoPE (+ 1/8 scale folded into q) + tf32 rounding; round v too
    {
        int totq = BB * SS * NH * 32;
        int totk = BB * SS * NKV * 32;
        rope_kernel<<<(totq + 255) / 256, 256>>>(q, fcos, fsin, 10, totq, 0.125f);
        rope_kernel<<<(totk + 255) / 256, 256>>>(k, fcos, fsin, 8, totk, 1.0f);
        int n4v = (BB * SS * NKV * HD) / 4;
        round_tf32_kernel<<<(n4v + 255) / 256, 256>>>((const float4*)v, (float4*)v, n4v);
    }

    // Attention (mma.sync tf32 + fp32 softmax)
    attn_kernel<<<dim3(SS / 64, NH, BB), 128>>>(q, k, v, att);

    // Output projection
    gemm_tf32_kernel<<<dim3(DM / 128, M / 128), 256, GEMM_SMEM>>>(att, woT, out, M, DM, DM);
}

// round 4
// speedup vs baseline: 4.9017x; 1.6447x over previous
#include <cuda_runtime.h>
#include <cstdint>

// Problem constants
#define BB 2
#define SS 2048
#define DM 2048
#define NH 32
#define NKV 8
#define HD 64

// ---------------------------------------------------------------------------
// Scratch (allocation-free rule: __device__ globals)
// ---------------------------------------------------------------------------
__device__ __align__(1024) float g_q[(size_t)BB * SS * NH * HD];
__device__ __align__(1024) float g_k[(size_t)BB * SS * NKV * HD];
__device__ __align__(1024) float g_v[(size_t)BB * SS * NKV * HD];
__device__ __align__(1024) float g_att[(size_t)BB * SS * NH * HD];
__device__ __align__(1024) float g_xr[(size_t)BB * SS * DM];
__device__ __align__(1024) float g_wqr[(size_t)DM * (NH * HD)];
__device__ __align__(1024) float g_wkr[(size_t)DM * (NKV * HD)];
__device__ __align__(1024) float g_wvr[(size_t)DM * (NKV * HD)];
__device__ __align__(1024) float g_wor[(size_t)DM * DM];

// ---------------------------------------------------------------------------
// Helpers
// ---------------------------------------------------------------------------
__device__ __forceinline__ uint32_t smem_u32(const void* p) {
    uint32_t a;
    asm("{ .reg .u64 t; cvta.to.shared.u64 t, %1; cvt.u32.u64 %0, t; }" : "=r"(a) : "l"(p));
    return a;
}
__device__ __forceinline__ float rna_tf32(float v) {
    uint32_t r;
    asm("cvt.rna.tf32.f32 %0, %1;" : "=r"(r) : "f"(v));
    return __uint_as_float(r);
}
__device__ __forceinline__ uint32_t rna_tf32_u(float v) {
    uint32_t r;
    asm("cvt.rna.tf32.f32 %0, %1;" : "=r"(r) : "f"(v));
    return r;
}
__device__ __forceinline__ void cp_async16(uint32_t smem, const void* gmem) {
    asm volatile("cp.async.cg.shared.global [%0], [%1], 16;" :: "r"(smem), "l"(gmem));
}
#define CP_COMMIT() asm volatile("cp.async.commit_group;" ::: "memory")
#define CP_WAIT(n)  asm volatile("cp.async.wait_group %0;" :: "n"(n) : "memory")

// m16n8k8 tf32 MMA (sm_80+ baseline; runs on Blackwell legacy HMMA pipe)
__device__ __forceinline__ void mma16n8k8(float* d, const uint32_t* a, const uint32_t* b) {
    asm volatile(
        "mma.sync.aligned.m16n8k8.row.col.f32.tf32.tf32.f32 "
        "{%0,%1,%2,%3}, {%4,%5,%6,%7}, {%8,%9}, {%0,%1,%2,%3};"
        : "+f"(d[0]), "+f"(d[1]), "+f"(d[2]), "+f"(d[3])
        : "r"(a[0]), "r"(a[1]), "r"(a[2]), "r"(a[3]), "r"(b[0]), "r"(b[1]));
}

// ---------------------------------------------------------------------------
// tf32 mma.sync GEMM: C[M,N] = A[M,K] @ B[K,N], both row-major, pre-rounded.
// BM=BN=128, BK=32, 256 threads / 8 warps (warp tile 32x64), 3-stage cp.async.
// A smem [128][36] (bank = 4m+k), B smem [32][136] (bank = 8k+n): conflict-free.
// ---------------------------------------------------------------------------
#define GASZ 4608            // A floats per stage (128*36)
#define GBSZ 4352            // B floats per stage (32*136)
#define GSTG (GASZ + GBSZ)   // 8960 floats
#define GEMM_SMEM (3 * GSTG * 4)

__global__ __launch_bounds__(256) void gemm_tf32_kernel(
    const float* __restrict__ A, const float* __restrict__ Bw,
    float* __restrict__ C, int M, int N, int K)
{
    extern __shared__ float sm[];
    const int tid = threadIdx.x;
    const int wid = tid >> 5, lid = tid & 31;
    const int wm = wid & 3, wn = wid >> 2;       // 4x2 warp grid
    const int lr = lid >> 2, lc = lid & 3;
    const int bm = blockIdx.y * 128, bn = blockIdx.x * 128;

    const float* Ag = A + (size_t)bm * K;
    const uint32_t sb = smem_u32(sm);

    float acc[2][8][4];
#pragma unroll
    for (int mt = 0; mt < 2; mt++)
#pragma unroll
        for (int nt = 0; nt < 8; nt++)
#pragma unroll
            for (int i = 0; i < 4; i++) acc[mt][nt][i] = 0.f;

    auto load_stage = [&](int s) {
        const int st = s - (s / 3) * 3;
        const float* Ab = Ag + s * 32;
        const float* Bb = Bw + (size_t)(s * 32) * N + bn;
#pragma unroll
        for (int i = 0; i < 4; i++) {
            int c = tid + i * 256;
            int ar = c >> 3, ac = (c & 7) * 4;
            cp_async16(sb + (uint32_t)(st * GSTG + ar * 36 + ac) * 4,
                       Ab + (size_t)ar * K + ac);
            int br = c >> 5, bc = (c & 31) * 4;
            cp_async16(sb + (uint32_t)(st * GSTG + GASZ + br * 136 + bc) * 4,
                       Bb + (size_t)br * N + bc);
        }
    };

    const int nk = K / 32;
#pragma unroll
    for (int s = 0; s < 3; s++) { if (s < nk) load_stage(s); CP_COMMIT(); }

    for (int s = 0; s < nk; s++) {
        CP_WAIT(2);
        __syncthreads();
        const int st = s - (s / 3) * 3;
        const float* As = sm + st * GSTG + (wm * 32 + lr) * 36 + lc;
#pragma unroll
        for (int kk = 0; kk < 4; kk++) {
            uint32_t af[2][4], bf[8][2];
#pragma unroll
            for (int mt = 0; mt < 2; mt++) {
                const float* p = As + mt * 16 * 36 + kk * 8;
                af[mt][0] = __float_as_uint(p[0]);
                af[mt][1] = __float_as_uint(p[8 * 36]);
                af[mt][2] = __float_as_uint(p[4]);
                af[mt][3] = __float_as_uint(p[8 * 36 + 4]);
            }
            const float* Bk = sm + st * GSTG + GASZ + (kk * 8 + lc) * 136 + wn * 64 + lr;
#pragma unroll
            for (int nt = 0; nt < 8; nt++) {
                bf[nt][0] = __float_as_uint(Bk[nt * 8]);
                bf[nt][1] = __float_as_uint(Bk[4 * 136 + nt * 8]);
            }
#pragma unroll
            for (int mt = 0; mt < 2; mt++)
#pragma unroll
                for (int nt = 0; nt < 8; nt++)
                    mma16n8k8(acc[mt][nt], af[mt], bf[nt]);
        }
        __syncthreads();
        if (s + 3 < nk) load_stage(s + 3);
        CP_COMMIT();
    }

#pragma unroll
    for (int mt = 0; mt < 2; mt++) {
        const int r0 = bm + wm * 32 + mt * 16 + lr;
#pragma unroll
        for (int nt = 0; nt < 8; nt++) {
            const int col = bn + wn * 64 + nt * 8 + lc * 2;
            *(float2*)&C[(size_t)r0 * N + col] =
                make_float2(acc[mt][nt][0], acc[mt][nt][1]);
            *(float2*)&C[(size_t)(r0 + 8) * N + col] =
                make_float2(acc[mt][nt][2], acc[mt][nt][3]);
        }
    }
}

// ---------------------------------------------------------------------------
// Elementwise fp32 -> tf32 (RNA)
// ---------------------------------------------------------------------------
__global__ void round_tf32_kernel(const float4* __restrict__ in,
                                  float4* __restrict__ out, int n4)
{
    int i = blockIdx.x * 256 + threadIdx.x;
    if (i >= n4) return;
    float4 v = in[i];
    v.x = rna_tf32(v.x); v.y = rna_tf32(v.y);
    v.z = rna_tf32(v.z); v.w = rna_tf32(v.w);
    out[i] = v;
}

// ---------------------------------------------------------------------------
// RoPE in-place + optional scale + tf32 RNA round
// ---------------------------------------------------------------------------
__global__ void rope_kernel(float* __restrict__ t,
                            const float* __restrict__ cs,
                            const float* __restrict__ sn,
                            int shift, int total, float scale)
{
    int i = blockIdx.x * 256 + threadIdx.x;
    if (i >= total) return;
    int p = i & 31;
    int s = (i >> shift) & (SS - 1);
    float2 v = *(float2*)(t + (size_t)i * 2);
    float c = cs[s * 32 + p];
    float si = sn[s * 32 + p];
    float2 o;
    o.x = rna_tf32(scale * (v.x * c - v.y * si));
    o.y = rna_tf32(scale * (v.x * si + v.y * c));
    *(float2*)(t + (size_t)i * 2) = o;
}

// ---------------------------------------------------------------------------
// Flash attention (causal, GQA) via mma.sync tf32.
// Block = 64 q-rows x head x batch; 4 warps, warp owns 16 rows, full 64 d.
// K rows stored PERMUTED (slot t holds key phi(t); phi(t)= t even? t/2 : t/2+4)
// so the S accumulator layout coincides with the PV A-fragment layout: no shfl.
// 2-stage cp.async double buffer for K/V tiles.
// ---------------------------------------------------------------------------
#define KS_F (64 * 68)
#define VS_F (64 * 72)
#define AST_F (KS_F + VS_F)
#define ATTN_SMEM (2 * AST_F * 4)

__global__ __launch_bounds__(128) void attn_kernel(
    const float* __restrict__ Q, const float* __restrict__ Kg,
    const float* __restrict__ Vg, float* __restrict__ O)
{
    extern __shared__ float sm[];
    const uint32_t sb = smem_u32(sm);

    const int m0 = blockIdx.x * 64;
    const int h = blockIdx.y;
    const int b = blockIdx.z;
    const int kvh = h >> 2;
    const int tid = threadIdx.x;
    const int w = tid >> 5, lid = tid & 31;
    const int lr = lid >> 2, lc = lid & 3;
    const int row0 = m0 + w * 16 + lr;

    const size_t kvs = NKV * HD;  // 512
    const float* Kbase = Kg + (size_t)b * SS * kvs + kvh * HD;
    const float* Vbase = Vg + (size_t)b * SS * kvs + kvh * HD;

    // Persistent Q fragments (scaled by 1/8, tf32-rounded in rope)
    uint32_t qa[8][4];
    {
        const float* q0 = Q + ((size_t)(b * SS + row0) * NH + h) * HD;
        const float* q1 = q0 + (size_t)8 * NH * HD;
#pragma unroll
        for (int kk = 0; kk < 8; kk++) {
            qa[kk][0] = __float_as_uint(q0[kk * 8 + lc]);
            qa[kk][1] = __float_as_uint(q1[kk * 8 + lc]);
            qa[kk][2] = __float_as_uint(q0[kk * 8 + lc + 4]);
            qa[kk][3] = __float_as_uint(q1[kk * 8 + lc + 4]);
        }
    }

    float oacc[8][4];
#pragma unroll
    for (int nt = 0; nt < 8; nt++)
#pragma unroll
        for (int i = 0; i < 4; i++) oacc[nt][i] = 0.f;
    float mst0 = -1e30f, mst1 = -1e30f, lst0 = 0.f, lst1 = 0.f;

    auto loadKV = [&](int n0, int st) {
        const uint32_t kso = (uint32_t)(st * AST_F) * 4;
        const uint32_t vso = (uint32_t)(st * AST_F + KS_F) * 4;
#pragma unroll
        for (int i = 0; i < 8; i++) {
            int c = tid + i * 128;
            int j = c >> 4;
            int cc = (c & 15) * 4;
            int j3 = j & 7;
            int dst = (j & ~7) | ((j3 < 4) ? (2 * j3) : (2 * j3 - 7));
            cp_async16(sb + kso + (uint32_t)(dst * 68 + cc) * 4,
                       Kbase + (size_t)(n0 + j) * kvs + cc);
            cp_async16(sb + vso + (uint32_t)(j * 72 + cc) * 4,
                       Vbase + (size_t)(n0 + j) * kvs + cc);
        }
    };

    const int niter = m0 / 64 + 1;
    loadKV(0, 0);
    CP_COMMIT();

    for (int it = 0; it < niter; it++) {
        const int n0 = it * 64;
        const int st = it & 1;
        if (it + 1 < niter) {
            loadKV(n0 + 64, st ^ 1);
            CP_COMMIT();
            CP_WAIT(1);
        } else {
            CP_WAIT(0);
        }
        __syncthreads();

        const float* Ks = sm + st * AST_F;
        const float* Vs = sm + st * AST_F + KS_F;

        float s[8][4];
#pragma unroll
        for (int nt = 0; nt < 8; nt++)
#pragma unroll
            for (int i = 0; i < 4; i++) s[nt][i] = 0.f;
#pragma unroll
        for (int kk = 0; kk < 8; kk++) {
#pragma unroll
            for (int nt = 0; nt < 8; nt++) {
                uint32_t kb[2];
                const float* p = &Ks[(nt * 8 + lr) * 68 + kk * 8 + lc];
                kb[0] = __float_as_uint(p[0]);
                kb[1] = __float_as_uint(p[4]);
                mma16n8k8(s[nt], qa[kk], kb);
            }
        }

        if (n0 == m0) {
#pragma unroll
            for (int nt = 0; nt < 8; nt++) {
                const int key0 = n0 + nt * 8 + lc;
                const int key1 = key0 + 4;
                if (key0 > row0) s[nt][0] = -1e30f;
                if (key1 > row0) s[nt][1] = -1e30f;
                if (key0 > row0 + 8) s[nt][2] = -1e30f;
                if (key1 > row0 + 8) s[nt][3] = -1e30f;
            }
        }

        float mx0 = -1e30f, mx1 = -1e30f;
#pragma unroll
        for (int nt = 0; nt < 8; nt++) {
            mx0 = fmaxf(mx0, fmaxf(s[nt][0], s[nt][1]));
            mx1 = fmaxf(mx1, fmaxf(s[nt][2], s[nt][3]));
        }
        mx0 = fmaxf(mx0, __shfl_xor_sync(0xffffffffu, mx0, 1));
        mx0 = fmaxf(mx0, __shfl_xor_sync(0xffffffffu, mx0, 2));
        mx1 = fmaxf(mx1, __shfl_xor_sync(0xffffffffu, mx1, 1));
        mx1 = fmaxf(mx1, __shfl_xor_sync(0xffffffffu, mx1, 2));
        const float mn0 = fmaxf(mst0, mx0), mn1 = fmaxf(mst1, mx1);
        const float corr0 = __expf(mst0 - mn0), corr1 = __expf(mst1 - mn1);
        mst0 = mn0; mst1 = mn1;
        float sum0 = 0.f, sum1 = 0.f;
#pragma unroll
        for (int nt = 0; nt < 8; nt++) {
            s[nt][0] = __expf(s[nt][0] - mn0); sum0 += s[nt][0];
            s[nt][1] = __expf(s[nt][1] - mn0); sum0 += s[nt][1];
            s[nt][2] = __expf(s[nt][2] - mn1); sum1 += s[nt][2];
            s[nt][3] = __expf(s[nt][3] - mn1); sum1 += s[nt][3];
        }
        sum0 += __shfl_xor_sync(0xffffffffu, sum0, 1);
        sum0 += __shfl_xor_sync(0xffffffffu, sum0, 2);
        sum1 += __shfl_xor_sync(0xffffffffu, sum1, 1);
        sum1 += __shfl_xor_sync(0xffffffffu, sum1, 2);
        lst0 = lst0 * corr0 + sum0;
        lst1 = lst1 * corr1 + sum1;
#pragma unroll
        for (int nt = 0; nt < 8; nt++) {
            oacc[nt][0] *= corr0; oacc[nt][1] *= corr0;
            oacc[nt][2] *= corr1; oacc[nt][3] *= corr1;
        }

#pragma unroll
        for (int kk = 0; kk < 8; kk++) {
            uint32_t pa[4];
            pa[0] = rna_tf32_u(s[kk][0]);
            pa[1] = rna_tf32_u(s[kk][2]);
            pa[2] = rna_tf32_u(s[kk][1]);
            pa[3] = rna_tf32_u(s[kk][3]);
#pragma unroll
            for (int nt = 0; nt < 8; nt++) {
                uint32_t vb[2];
                const float* p = &Vs[(kk * 8 + lc) * 72 + nt * 8 + lr];
                vb[0] = __float_as_uint(p[0]);
                vb[1] = __float_as_uint(p[4 * 72]);
                mma16n8k8(oacc[nt], pa, vb);
            }
        }
        __syncthreads();
    }

    const float inv0 = 1.f / lst0, inv1 = 1.f / lst1;
    float* o0 = O + ((size_t)(b * SS + row0) * NH + h) * HD;
    float* o1 = o0 + (size_t)8 * NH * HD;
#pragma unroll
    for (int nt = 0; nt < 8; nt++) {
        const int col = nt * 8 + lc * 2;
        *(float2*)&o0[col] = make_float2(rna_tf32(oacc[nt][0] * inv0),
                                         rna_tf32(oacc[nt][1] * inv0));
        *(float2*)&o1[col] = make_float2(rna_tf32(oacc[nt][2] * inv1),
                                         rna_tf32(oacc[nt][3] * inv1));
    }
}

// ---------------------------------------------------------------------------
// Launch. inputs: 0=x, 1=freqs_cos, 2=freqs_sin, 3=mask(unused),
//                 4=wq, 5=wk, 6=wv, 7=wo
// ---------------------------------------------------------------------------
extern "C" void kernel_launch(void* const* d_in, const int* in_sizes, int n_in,
                              void* d_out, int out_size)
{
    const float* x = (const float*)d_in[0];
    const float* fcos = (const float*)d_in[1];
    const float* fsin = (const float*)d_in[2];
    const float* wq = (const float*)d_in[4];
    const float* wk = (const float*)d_in[5];
    const float* wv = (const float*)d_in[6];
    const float* wo = (const float*)d_in[7];
    float* out = (float*)d_out;

    float *q, *k, *v, *att, *xr, *wqr, *wkr, *wvr, *wor;
    cudaGetSymbolAddress((void**)&q, g_q);
    cudaGetSymbolAddress((void**)&k, g_k);
    cudaGetSymbolAddress((void**)&v, g_v);
    cudaGetSymbolAddress((void**)&att, g_att);
    cudaGetSymbolAddress((void**)&xr, g_xr);
    cudaGetSymbolAddress((void**)&wqr, g_wqr);
    cudaGetSymbolAddress((void**)&wkr, g_wkr);
    cudaGetSymbolAddress((void**)&wvr, g_wvr);
    cudaGetSymbolAddress((void**)&wor, g_wor);

    static bool attr_set = false;
    if (!attr_set) {
        cudaFuncSetAttribute(gemm_tf32_kernel,
                             cudaFuncAttributeMaxDynamicSharedMemorySize, GEMM_SMEM);
        cudaFuncSetAttribute(attn_kernel,
                             cudaFuncAttributeMaxDynamicSharedMemorySize, ATTN_SMEM);
        attr_set = true;
    }

    const int M = BB * SS;  // 4096

    {
        int n4;
        n4 = (BB * SS * DM) / 4;
        round_tf32_kernel<<<(n4 + 255) / 256, 256>>>((const float4*)x, (float4*)xr, n4);
        n4 = (DM * NH * HD) / 4;
        round_tf32_kernel<<<(n4 + 255) / 256, 256>>>((const float4*)wq, (float4*)wqr, n4);
        n4 = (DM * NKV * HD) / 4;
        round_tf32_kernel<<<(n4 + 255) / 256, 256>>>((const float4*)wk, (float4*)wkr, n4);
        round_tf32_kernel<<<(n4 + 255) / 256, 256>>>((const float4*)wv, (float4*)wvr, n4);
        n4 = (DM * DM) / 4;
        round_tf32_kernel<<<(n4 + 255) / 256, 256>>>((const float4*)wo, (float4*)wor, n4);
    }

    gemm_tf32_kernel<<<dim3((NH * HD) / 128, M / 128), 256, GEMM_SMEM>>>(xr, wqr, q, M, NH * HD, DM);
    gemm_tf32_kernel<<<dim3((NKV * HD) / 128, M / 128), 256, GEMM_SMEM>>>(xr, wkr, k, M, NKV * HD, DM);
    gemm_tf32_kernel<<<dim3((NKV * HD) / 128, M / 128), 256, GEMM_SMEM>>>(xr, wvr, v, M, NKV * HD, DM);

    {
        int totq = BB * SS * NH * 32;
        int totk = BB * SS * NKV * 32;
        rope_kernel<<<(totq + 255) / 256, 256>>>(q, fcos, fsin, 10, totq, 0.125f);
        rope_kernel<<<(totk + 255) / 256, 256>>>(k, fcos, fsin, 8, totk, 1.0f);
        int n4v = (BB * SS * NKV * HD) / 4;
        round_tf32_kernel<<<(n4v + 255) / 256, 256>>>((const float4*)v, (float4*)v, n4v);
    }

    attn_kernel<<<dim3(SS / 64, NH, BB), 128, ATTN_SMEM>>>(q, k, v, att);

    gemm_tf32_kernel<<<dim3(DM / 128, M / 128), 256, GEMM_SMEM>>>(att, wor, out, M, DM, DM);
}